// round 16
// baseline (speedup 1.0000x reference)
#include <cuda_runtime.h>
#include <math.h>

typedef unsigned long long ull;
typedef unsigned int uint32;

#define NPTS 16384
#define KNB 32
#define CCH 64
#define PPB 4          // points per block
#define NTHREADS 256
#define H1S 68         // h1 row stride: conflict-free fragments
#define WGS 68         // WgP row stride (permuted cols), 16B-aligned rows
#define WPS 68         // WpP row stride
#define GS  20         // geo row stride: conflict-free A fragments
#define WO2S 130       // woutP row stride in floats (pair-major), bank-spread
#define EPSF 1e-5f

// ---- packed fp32x2 helpers ----
__device__ __forceinline__ void fma2(ull& d, ull a, ull b) {
  asm("fma.rn.f32x2 %0, %1, %2, %0;" : "+l"(d) : "l"(a), "l"(b));
}
__device__ __forceinline__ float2 unpack2(ull v) {
  float2 r; asm("mov.b64 {%0, %1}, %2;" : "=f"(r.x), "=f"(r.y) : "l"(v)); return r;
}

// ---- tf32 MMA: D += A(16x8) * B(8x8), fp32 accumulate ----
__device__ __forceinline__ void mma_tf32(float* d,
    uint32 a0, uint32 a1, uint32 a2, uint32 a3, uint32 b0, uint32 b1) {
  asm("mma.sync.aligned.m16n8k8.row.col.f32.tf32.tf32.f32 "
      "{%0,%1,%2,%3}, {%4,%5,%6,%7}, {%8,%9}, {%0,%1,%2,%3};"
      : "+f"(d[0]), "+f"(d[1]), "+f"(d[2]), "+f"(d[3])
      : "r"(a0), "r"(a1), "r"(a2), "r"(a3), "r"(b0), "r"(b1));
}
__device__ __forceinline__ void split_tf32(float x, uint32& hi, uint32& lo) {
  hi = __float_as_uint(x) & 0xFFFFE000u;
  lo = __float_as_uint(x - __uint_as_float(hi));
}
// named barrier: 2 warps of one point
__device__ __forceinline__ void bar_pt(int id) {
  asm volatile("bar.sync %0, 64;" :: "r"(id) : "memory");
}

struct __align__(16) Smem {
  float WpP[16][WPS];            // [g][g4*8+t8] permuted: rows 0-9 = a1*W_pos^T, row 10 = bias1
  union {                        // WgP (phases 1-2) then woutP (phases 3-4)
    float WgP[CCH][WGS];         // [c][g4*8+t8] = a2[d]*W_gcm[d][c], d = t8*8+g4
    float woutP_raw[32 * WO2S];  // [(c>>1)*WO2S + 2o + (c&1)] = W_out[o][c]
  } w;
  float a1s[CCH], a2s[CCH], bias1a[CCH], bias2[CCH];
  float Watt[KNB];
  int   nidx[PPB][KNB];
  float h1[PPB][KNB * H1S];
  float geo[PPB][KNB][GS];       // NOT unioned: points skew freely
  struct {
    float ps[PPB][2][CCH];
    float pm[PPB][2][CCH];
    float resv[PPB][CCH];
    float redC[PPB][2], redD[PPB][2];
  } t;
};

__global__ __launch_bounds__(NTHREADS, 3)
void bridgenet_kernel(
    const float* __restrict__ points,
    const float* __restrict__ features,
    const int*   __restrict__ gidx,
    const float* __restrict__ W_pos,
    const float* __restrict__ b_pos,
    const float* __restrict__ bn1_g, const float* __restrict__ bn1_b,
    const float* __restrict__ bn1_m, const float* __restrict__ bn1_v,
    const float* __restrict__ W_gcm,
    const float* __restrict__ b_gcm,
    const float* __restrict__ bn2_g, const float* __restrict__ bn2_b,
    const float* __restrict__ bn2_m, const float* __restrict__ bn2_v,
    const float* __restrict__ W_att,
    const float* __restrict__ W_out,
    const float* __restrict__ b_out,
    const float* __restrict__ ln_g, const float* __restrict__ ln_b,
    float* __restrict__ out)
{
  extern __shared__ char smem_raw[];
  Smem& s = *reinterpret_cast<Smem*>(smem_raw);
  const int tid = threadIdx.x;

  const int pt = tid >> 6;           // point within block
  const int tp = tid & 63;           // thread within point
  const int wip = tp >> 5;           // warp within point
  const int p  = blockIdx.x * PPB + pt;
  const int bb = p >> 14;            // N = 16384
  const int nn = p & (NPTS - 1);
  const int base_pn = bb * NPTS + nn;

  // ---- Phase 0: BN folding + neighbor idx + geo staging -------------------
  if (tid < CCH) {
    float a1 = bn1_g[tid] * rsqrtf(bn1_v[tid] + EPSF);
    s.a1s[tid] = a1;
    s.bias1a[tid] = a1 * (b_pos[tid] - bn1_m[tid]) + bn1_b[tid];
    float a2 = bn2_g[tid] * rsqrtf(bn2_v[tid] + EPSF);
    s.a2s[tid] = a2;
    s.bias2[tid] = a2 * (b_gcm[tid] - bn2_m[tid]) + bn2_b[tid];
  }
  if (tid >= CCH && tid < CCH + KNB) s.Watt[tid - CCH] = W_att[tid - CCH];

  if (tp < KNB) {                    // one thread per (pt, neighbor)
    const int idx = gidx[base_pn * KNB + tp];
    s.nidx[pt][tp] = idx;
    const int gb = bb * NPTS + idx;
    const float xix = points[base_pn * 3 + 0];
    const float xiy = points[base_pn * 3 + 1];
    const float xiz = points[base_pn * 3 + 2];
    const float gx = points[gb * 3 + 0];
    const float gy = points[gb * 3 + 1];
    const float gz = points[gb * 3 + 2];
    const float dx = xix - gx, dy = xiy - gy, dz = xiz - gz;
    const float dist = sqrtf(dx*dx + dy*dy + dz*dz);
    float* gr = &s.geo[pt][tp][0];
    gr[0] = xix; gr[1] = xiy; gr[2] = xiz;
    gr[3] = gx;  gr[4] = gy;  gr[5] = gz;
    gr[6] = dx;  gr[7] = dy;  gr[8] = dz;
    gr[9] = dist; gr[10] = 1.0f;               // pairs with bias row of WpP
    gr[11] = 0.0f; gr[12] = 0.0f; gr[13] = 0.0f; gr[14] = 0.0f; gr[15] = 0.0f;
  }
  __syncthreads();                   // sync1

  // ---- Weight scatter (permuted layouts) + feature gather into h1 ---------
  for (int i = tid; i < 16 * CCH; i += NTHREADS) {
    const int g = i >> 6, c = i & 63;
    float v = 0.0f;
    if (g < 10)       v = s.a1s[c] * W_pos[c * 10 + g];
    else if (g == 10) v = s.bias1a[c];
    s.WpP[g][(c & 7) * 8 + (c >> 3)] = v;      // permuted: col' = g4*8 + t8
  }
  for (int i = tid; i < CCH * CCH; i += NTHREADS) {
    const int d = i >> 6, c = i & 63;
    s.w.WgP[c][(d & 7) * 8 + (d >> 3)] = s.a2s[d] * W_gcm[i];  // W_gcm[d][c]
  }
  {
    const int chunk = tp & 15;                // 16B chunk within feature row
    const int rsub  = tp >> 4;                // 0..3
    #pragma unroll
    for (int j = 0; j < 8; ++j) {
      const int row = rsub + 4 * j;           // neighbor 0..31
      const int gb  = bb * NPTS + s.nidx[pt][row];
      const float4 v = *reinterpret_cast<const float4*>(features + gb * CCH + chunk * 4);
      *reinterpret_cast<float4*>(&s.h1[pt][row * H1S + chunk * 4]) = v;
    }
  }
  __syncthreads();                   // sync2

  const int lane = tp & 31;
  const int g4 = lane >> 2;          // 0..7
  const int q4 = lane & 3;           // 0..3
  const int mbase = wip * 16;

  // ---- Phase 1: pos-encoding GEMM via tf32 MMA; h1 += relu(enc) -----------
  {
    float acc[8][4];
    #pragma unroll
    for (int t8 = 0; t8 < 8; ++t8)
      #pragma unroll
      for (int j = 0; j < 4; ++j) acc[t8][j] = 0.0f;

    const float* geob = &s.geo[pt][0][0];
    #pragma unroll
    for (int ks = 0; ks < 2; ++ks) {
      const int r0 = (mbase + g4) * GS + ks * 8 + q4;
      const int r1 = r0 + 8 * GS;
      const float a0 = geob[r0],      a1v = geob[r1];
      const float a2f = geob[r0 + 4], a3v = geob[r1 + 4];
      uint32 ah0, al0, ah1, al1, ah2, al2, ah3, al3;
      split_tf32(a0,  ah0, al0);
      split_tf32(a1v, ah1, al1);
      split_tf32(a2f, ah2, al2);
      split_tf32(a3v, ah3, al3);

      const float* wr0 = &s.WpP[ks * 8 + q4][g4 * 8];
      const float* wr1 = &s.WpP[ks * 8 + q4 + 4][g4 * 8];
      float4 bqa = *reinterpret_cast<const float4*>(wr0);
      float4 bqb = *reinterpret_cast<const float4*>(wr0 + 4);
      float4 bra = *reinterpret_cast<const float4*>(wr1);
      float4 brb = *reinterpret_cast<const float4*>(wr1 + 4);
      const float bq[8] = {bqa.x, bqa.y, bqa.z, bqa.w, bqb.x, bqb.y, bqb.z, bqb.w};
      const float br[8] = {bra.x, bra.y, bra.z, bra.w, brb.x, brb.y, brb.z, brb.w};

      #pragma unroll
      for (int t8 = 0; t8 < 8; ++t8) {
        uint32 bh0, bl0, bh1, bl1;
        split_tf32(bq[t8], bh0, bl0);
        split_tf32(br[t8], bh1, bl1);
        mma_tf32(acc[t8], ah0, ah1, ah2, ah3, bh0, bh1);
        mma_tf32(acc[t8], ah0, ah1, ah2, ah3, bl0, bl1);
        mma_tf32(acc[t8], al0, al1, al2, al3, bh0, bh1);
      }
    }

    // h1[row][col] = feature + relu(enc): own-warp rows only
    float* h1b = &s.h1[pt][0];
    #pragma unroll
    for (int t8 = 0; t8 < 8; ++t8) {
      const int n0 = t8 * 8 + 2 * q4;
      float2* p0 = reinterpret_cast<float2*>(&h1b[(mbase + g4) * H1S + n0]);
      float2* p1 = reinterpret_cast<float2*>(&h1b[(mbase + g4 + 8) * H1S + n0]);
      float2 f0 = *p0, f1 = *p1;
      f0.x += fmaxf(acc[t8][0], 0.0f);
      f0.y += fmaxf(acc[t8][1], 0.0f);
      f1.x += fmaxf(acc[t8][2], 0.0f);
      f1.y += fmaxf(acc[t8][3], 0.0f);
      *p0 = f0; *p1 = f1;
    }
  }
  __syncwarp();                      // phase1->2: own-warp rows only

  // ---- Phase 2: h2 GEMM via tf32 MMA (3-pass hi/lo) -----------------------
  {
    float acc[8][4];
    #pragma unroll
    for (int t8 = 0; t8 < 8; ++t8)
      #pragma unroll
      for (int j = 0; j < 4; ++j) acc[t8][j] = 0.0f;

    const float* h1b = &s.h1[pt][0];
    #pragma unroll
    for (int ks = 0; ks < 8; ++ks) {
      const int r0 = (mbase + g4) * H1S + ks * 8 + q4;
      const int r1 = r0 + 8 * H1S;
      const float a0 = h1b[r0],      a1v = h1b[r1];
      const float a2f = h1b[r0 + 4], a3v = h1b[r1 + 4];
      uint32 ah0, al0, ah1, al1, ah2, al2, ah3, al3;
      split_tf32(a0,  ah0, al0);
      split_tf32(a1v, ah1, al1);
      split_tf32(a2f, ah2, al2);
      split_tf32(a3v, ah3, al3);

      const float* wr0 = &s.w.WgP[ks * 8 + q4][g4 * 8];
      const float* wr1 = &s.w.WgP[ks * 8 + q4 + 4][g4 * 8];
      float4 bqa = *reinterpret_cast<const float4*>(wr0);
      float4 bqb = *reinterpret_cast<const float4*>(wr0 + 4);
      float4 bra = *reinterpret_cast<const float4*>(wr1);
      float4 brb = *reinterpret_cast<const float4*>(wr1 + 4);
      const float bq[8] = {bqa.x, bqa.y, bqa.z, bqa.w, bqb.x, bqb.y, bqb.z, bqb.w};
      const float br[8] = {bra.x, bra.y, bra.z, bra.w, brb.x, brb.y, brb.z, brb.w};

      #pragma unroll
      for (int t8 = 0; t8 < 8; ++t8) {
        uint32 bh0, bl0, bh1, bl1;
        split_tf32(bq[t8], bh0, bl0);
        split_tf32(br[t8], bh1, bl1);
        mma_tf32(acc[t8], ah0, ah1, ah2, ah3, bh0, bh1);
        mma_tf32(acc[t8], ah0, ah1, ah2, ah3, bl0, bl1);
        mma_tf32(acc[t8], al0, al1, al2, al3, bh0, bh1);
      }
    }

    // Epilogue: bias + ReLU, attention dot over k, max over k
    const float wv0 = s.Watt[mbase + g4];
    const float wv1 = s.Watt[mbase + g4 + 8];
    #pragma unroll
    for (int t8 = 0; t8 < 8; ++t8) {
      const int n0 = t8 * 8 + 2 * q4;
      const float b0 = s.bias2[n0], b1 = s.bias2[n0 + 1];
      const float h00 = fmaxf(acc[t8][0] + b0, 0.0f);
      const float h01 = fmaxf(acc[t8][1] + b1, 0.0f);
      const float h10 = fmaxf(acc[t8][2] + b0, 0.0f);
      const float h11 = fmaxf(acc[t8][3] + b1, 0.0f);
      float spa = h00 * wv0 + h10 * wv1;
      float spb = h01 * wv0 + h11 * wv1;
      float mpa = fmaxf(h00, h10);
      float mpb = fmaxf(h01, h11);
      #pragma unroll
      for (int m = 4; m <= 16; m <<= 1) {
        spa += __shfl_xor_sync(0xffffffffu, spa, m);
        spb += __shfl_xor_sync(0xffffffffu, spb, m);
        mpa = fmaxf(mpa, __shfl_xor_sync(0xffffffffu, mpa, m));
        mpb = fmaxf(mpb, __shfl_xor_sync(0xffffffffu, mpb, m));
      }
      if (g4 == 0) {
        *reinterpret_cast<float2*>(&s.t.ps[pt][wip][n0]) = make_float2(spa, spb);
        *reinterpret_cast<float2*>(&s.t.pm[pt][wip][n0]) = make_float2(mpa, mpb);
      }
    }
  }
  __syncthreads();                   // sync3: all phase-2 done; WgP dead

  // ---- Phase 3: woutP fill (into WgP space) + softmax/pool/residual -------
  const int o = tp;
  const float bo = b_out[o];                   // prefetch phase-4 params
  const float lg = ln_g[o];
  const float lb = ln_b[o];
  {
    float* wp = s.w.woutP_raw;                 // paired layout, conflict-free STS
    for (int i = tid; i < CCH * CCH; i += NTHREADS) {
      const int oo = i >> 6, c = i & 63;
      wp[(c >> 1) * WO2S + oo * 2 + (c & 1)] = W_out[i];
    }
  }
  {
    const int c0 = lane, c1 = lane + 32;
    const float f_res = features[base_pn * CCH + o];   // residual, coalesced
    float sv0 = s.t.ps[pt][0][c0] + s.t.ps[pt][1][c0]; // b_att softmax-invariant
    float sv1 = s.t.ps[pt][0][c1] + s.t.ps[pt][1][c1];
    float mv0 = fmaxf(s.t.pm[pt][0][c0], s.t.pm[pt][1][c0]);
    float mv1 = fmaxf(s.t.pm[pt][0][c1], s.t.pm[pt][1][c1]);

    float mx = fmaxf(sv0, sv1);                // full 64-channel max, intra-warp
    #pragma unroll
    for (int m = 16; m >= 1; m >>= 1)
      mx = fmaxf(mx, __shfl_xor_sync(0xffffffffu, mx, m));

    const float e0 = expf(sv0 - mx);
    const float e1 = expf(sv1 - mx);
    float se = e0 + e1;
    #pragma unroll
    for (int m = 16; m >= 1; m >>= 1)
      se += __shfl_xor_sync(0xffffffffu, se, m);

    const float ec = wip ? e1 : e0;            // channel o = lane + 32*wip
    const float mc = wip ? mv1 : mv0;
    s.t.resv[pt][o] = (ec / se) * mc + f_res;
  }
  __syncthreads();                   // sync4: woutP + resv published

  // ---- Phase 4: out GEMM (f32x2, paired weights) + LayerNorm + ReLU -------
  {
    const float* wp = s.w.woutP_raw;
    ull e2 = 0ULL;
    #pragma unroll
    for (int c4 = 0; c4 < 16; ++c4) {
      const ull r01 = *reinterpret_cast<const ull*>(&s.t.resv[pt][c4 * 4]);     // bcast
      const ull r23 = *reinterpret_cast<const ull*>(&s.t.resv[pt][c4 * 4 + 2]);
      const ull w01 = *reinterpret_cast<const ull*>(&wp[(2 * c4) * WO2S + 2 * o]);
      const ull w23 = *reinterpret_cast<const ull*>(&wp[(2 * c4 + 1) * WO2S + 2 * o]);
      fma2(e2, r01, w01);
      fma2(e2, r23, w23);
    }
    float2 ee = unpack2(e2);
    float acc = ee.x + ee.y + bo;

    float sum = acc, sq = acc * acc;
    #pragma unroll
    for (int m = 16; m >= 1; m >>= 1) {
      sum += __shfl_xor_sync(0xffffffffu, sum, m);
      sq  += __shfl_xor_sync(0xffffffffu, sq, m);
    }
    if (lane == 0) { s.t.redC[pt][wip] = sum; s.t.redD[pt][wip] = sq; }
    bar_pt(1 + pt);                  // point-local exchange
    sum = s.t.redC[pt][0] + s.t.redC[pt][1];
    sq  = s.t.redD[pt][0] + s.t.redD[pt][1];

    const float mu  = sum * (1.0f / 64.0f);
    const float var = sq * (1.0f / 64.0f) - mu * mu;
    const float r   = rsqrtf(var + EPSF);
    const float y   = lg * (acc - mu) * r + lb;
    out[base_pn * CCH + o] = fmaxf(y, 0.0f);
  }
}

extern "C" void kernel_launch(void* const* d_in, const int* in_sizes, int n_in,
                              void* d_out, int out_size) {
  const float* points   = (const float*)d_in[0];
  const float* features = (const float*)d_in[1];
  const int*   gidx     = (const int*)  d_in[2];
  const float* W_pos    = (const float*)d_in[3];
  const float* b_pos    = (const float*)d_in[4];
  const float* bn1_g    = (const float*)d_in[5];
  const float* bn1_b    = (const float*)d_in[6];
  const float* bn1_m    = (const float*)d_in[7];
  const float* bn1_v    = (const float*)d_in[8];
  const float* W_gcm    = (const float*)d_in[9];
  const float* b_gcm    = (const float*)d_in[10];
  const float* bn2_g    = (const float*)d_in[11];
  const float* bn2_b    = (const float*)d_in[12];
  const float* bn2_m    = (const float*)d_in[13];
  const float* bn2_v    = (const float*)d_in[14];
  const float* W_att    = (const float*)d_in[15];
  // d_in[16] = b_att (scalar): softmax-invariant, unused.
  const float* W_out    = (const float*)d_in[17];
  const float* b_out    = (const float*)d_in[18];
  const float* ln_g     = (const float*)d_in[19];
  const float* ln_b     = (const float*)d_in[20];
  float* out = (float*)d_out;

  const size_t smem = sizeof(Smem);
  cudaFuncSetAttribute((const void*)bridgenet_kernel,
                       cudaFuncAttributeMaxDynamicSharedMemorySize, (int)smem);

  const int total_pts = 2 * NPTS;             // 32768
  dim3 grid(total_pts / PPB);                 // 8192 blocks
  bridgenet_kernel<<<grid, NTHREADS, smem>>>(
      points, features, gidx, W_pos, b_pos,
      bn1_g, bn1_b, bn1_m, bn1_v,
      W_gcm, b_gcm, bn2_g, bn2_b, bn2_m, bn2_v,
      W_att, W_out, b_out, ln_g, ln_b, out);
}

// round 17
// speedup vs baseline: 1.0727x; 1.0727x over previous
#include <cuda_runtime.h>
#include <math.h>

typedef unsigned long long ull;
typedef unsigned int uint32;

#define NPTS 16384
#define KNB 32
#define CCH 64
#define PPB 4          // points per block
#define NTHREADS 256
#define H1S 68         // h1 row stride: conflict-free fragments + column reads
#define WGS 72         // Wg2 row stride: conflict-free B fragments
#define WPS 72         // WpT row stride
#define GS  20         // geo row stride: conflict-free A fragments
#define WO2S 130       // woutP row stride (pair-major floats)
#define EPSF 1e-5f

// ---- packed fp32x2 helpers (phase 4) ----
__device__ __forceinline__ void fma2(ull& d, ull a, ull b) {
  asm("fma.rn.f32x2 %0, %1, %2, %0;" : "+l"(d) : "l"(a), "l"(b));
}
__device__ __forceinline__ float2 unpack2(ull v) {
  float2 r; asm("mov.b64 {%0, %1}, %2;" : "=f"(r.x), "=f"(r.y) : "l"(v)); return r;
}

// ---- tf32 MMA: D += A(16x8) * B(8x8), fp32 accumulate ----
__device__ __forceinline__ void mma_tf32(float* d,
    uint32 a0, uint32 a1, uint32 a2, uint32 a3, uint32 b0, uint32 b1) {
  asm("mma.sync.aligned.m16n8k8.row.col.f32.tf32.tf32.f32 "
      "{%0,%1,%2,%3}, {%4,%5,%6,%7}, {%8,%9}, {%0,%1,%2,%3};"
      : "+f"(d[0]), "+f"(d[1]), "+f"(d[2]), "+f"(d[3])
      : "r"(a0), "r"(a1), "r"(a2), "r"(a3), "r"(b0), "r"(b1));
}
__device__ __forceinline__ void split_tf32(float x, uint32& hi, uint32& lo) {
  hi = __float_as_uint(x) & 0xFFFFE000u;
  lo = __float_as_uint(x - __uint_as_float(hi));
}
// named barrier: 2 warps of one point
__device__ __forceinline__ void bar_pt(int id) {
  asm volatile("bar.sync %0, 64;" :: "r"(id) : "memory");
}

struct __align__(16) Smem {
  float WpT[16][WPS];            // [g][c]: rows 0-9 = a1*W_pos^T, row 10 = bias1, rest 0
  union {                        // Wg2 (phases 1-2) then woutP (phases 3-4)
    float Wg2[CCH][WGS];         // [c][d] = a2[d]*W_gcm[d][c]
    float woutP_raw[32 * WO2S];  // [(c>>1)*WO2S + 2o + (c&1)] = W_out[o][c]
  } w;
  float a1s[CCH], a2s[CCH], bias1a[CCH], bias2[CCH];
  float Watt[KNB];
  int   nidx[PPB][KNB];
  float h1[PPB][KNB * H1S];      // features+enc (phase 1-2 A), then h2 (reduction)
  float geo[PPB][KNB][GS];
  float resv[PPB][CCH];
  float2 redC[PPB][2];           // softmax (mx,sum) then LN (sum,sq)
};

__global__ __launch_bounds__(NTHREADS, 3)
void bridgenet_kernel(
    const float* __restrict__ points,
    const float* __restrict__ features,
    const int*   __restrict__ gidx,
    const float* __restrict__ W_pos,
    const float* __restrict__ b_pos,
    const float* __restrict__ bn1_g, const float* __restrict__ bn1_b,
    const float* __restrict__ bn1_m, const float* __restrict__ bn1_v,
    const float* __restrict__ W_gcm,
    const float* __restrict__ b_gcm,
    const float* __restrict__ bn2_g, const float* __restrict__ bn2_b,
    const float* __restrict__ bn2_m, const float* __restrict__ bn2_v,
    const float* __restrict__ W_att,
    const float* __restrict__ W_out,
    const float* __restrict__ b_out,
    const float* __restrict__ ln_g, const float* __restrict__ ln_b,
    float* __restrict__ out)
{
  extern __shared__ char smem_raw[];
  Smem& s = *reinterpret_cast<Smem*>(smem_raw);
  const int tid = threadIdx.x;

  const int pt = tid >> 6;           // point within block
  const int tp = tid & 63;           // thread within point
  const int wip = tp >> 5;           // warp within point
  const int p  = blockIdx.x * PPB + pt;
  const int bb = p >> 14;            // N = 16384
  const int nn = p & (NPTS - 1);
  const int base_pn = bb * NPTS + nn;

  // ---- Phase 0: BN folding + neighbor idx + geo staging -------------------
  if (tid < CCH) {
    float a1 = bn1_g[tid] * rsqrtf(bn1_v[tid] + EPSF);
    s.a1s[tid] = a1;
    s.bias1a[tid] = a1 * (b_pos[tid] - bn1_m[tid]) + bn1_b[tid];
    float a2 = bn2_g[tid] * rsqrtf(bn2_v[tid] + EPSF);
    s.a2s[tid] = a2;
    s.bias2[tid] = a2 * (b_gcm[tid] - bn2_m[tid]) + bn2_b[tid];
  }
  if (tid >= CCH && tid < CCH + KNB) s.Watt[tid - CCH] = W_att[tid - CCH];

  if (tp < KNB) {                    // one thread per (pt, neighbor)
    const int idx = gidx[base_pn * KNB + tp];
    s.nidx[pt][tp] = idx;
    const int gb = bb * NPTS + idx;
    const float xix = points[base_pn * 3 + 0];
    const float xiy = points[base_pn * 3 + 1];
    const float xiz = points[base_pn * 3 + 2];
    const float gx = points[gb * 3 + 0];
    const float gy = points[gb * 3 + 1];
    const float gz = points[gb * 3 + 2];
    const float dx = xix - gx, dy = xiy - gy, dz = xiz - gz;
    const float dist = sqrtf(dx*dx + dy*dy + dz*dz);
    float* gr = &s.geo[pt][tp][0];
    gr[0] = xix; gr[1] = xiy; gr[2] = xiz;
    gr[3] = gx;  gr[4] = gy;  gr[5] = gz;
    gr[6] = dx;  gr[7] = dy;  gr[8] = dz;
    gr[9] = dist; gr[10] = 1.0f;               // pairs with bias row of WpT
    gr[11] = 0.0f; gr[12] = 0.0f; gr[13] = 0.0f; gr[14] = 0.0f; gr[15] = 0.0f;
  }
  __syncthreads();                   // sync1

  // ---- Weight scatter + line-contiguous feature gather into h1 ------------
  for (int i = tid; i < 16 * CCH; i += NTHREADS) {
    const int g = i >> 6, c = i & 63;
    float v = 0.0f;
    if (g < 10)       v = s.a1s[c] * W_pos[c * 10 + g];
    else if (g == 10) v = s.bias1a[c];
    s.WpT[g][c] = v;
  }
  for (int i = tid; i < CCH * CCH; i += NTHREADS) {
    const int d = i >> 6, c = i & 63;
    s.w.Wg2[c][d] = s.a2s[d] * W_gcm[i];      // W_gcm[d][c]
  }
  {
    const int chunk = tp & 15;                // 16B chunk within feature row
    const int rsub  = tp >> 4;                // 0..3
    #pragma unroll
    for (int j = 0; j < 8; ++j) {
      const int row = rsub + 4 * j;           // neighbor 0..31
      const int gb  = bb * NPTS + s.nidx[pt][row];
      const float4 v = *reinterpret_cast<const float4*>(features + gb * CCH + chunk * 4);
      *reinterpret_cast<float4*>(&s.h1[pt][row * H1S + chunk * 4]) = v;
    }
  }
  __syncthreads();                   // sync2

  const int lane = tp & 31;
  const int g4 = lane >> 2;          // 0..7
  const int q4 = lane & 3;           // 0..3
  const int mbase = wip * 16;

  // ---- Phase 1: pos-encoding GEMM via tf32 MMA; h1 += relu(enc) -----------
  {
    float acc[8][4];
    #pragma unroll
    for (int t8 = 0; t8 < 8; ++t8)
      #pragma unroll
      for (int j = 0; j < 4; ++j) acc[t8][j] = 0.0f;

    const float* geob = &s.geo[pt][0][0];
    #pragma unroll
    for (int ks = 0; ks < 2; ++ks) {
      const int r0 = (mbase + g4) * GS + ks * 8 + q4;
      const int r1 = r0 + 8 * GS;
      const float a0 = geob[r0],      a1v = geob[r1];
      const float a2f = geob[r0 + 4], a3v = geob[r1 + 4];
      uint32 ah0, al0, ah1, al1, ah2, al2, ah3, al3;
      split_tf32(a0,  ah0, al0);
      split_tf32(a1v, ah1, al1);
      split_tf32(a2f, ah2, al2);
      split_tf32(a3v, ah3, al3);
      #pragma unroll
      for (int t8 = 0; t8 < 8; ++t8) {
        const float b0 = s.WpT[ks * 8 + q4][t8 * 8 + g4];
        const float b1 = s.WpT[ks * 8 + q4 + 4][t8 * 8 + g4];
        uint32 bh0, bl0, bh1, bl1;
        split_tf32(b0, bh0, bl0);
        split_tf32(b1, bh1, bl1);
        mma_tf32(acc[t8], ah0, ah1, ah2, ah3, bh0, bh1);
        mma_tf32(acc[t8], ah0, ah1, ah2, ah3, bl0, bl1);
        mma_tf32(acc[t8], al0, al1, al2, al3, bh0, bh1);
      }
    }

    // h1[row][col] = feature + relu(enc): own-warp rows only
    float* h1b = &s.h1[pt][0];
    #pragma unroll
    for (int t8 = 0; t8 < 8; ++t8) {
      const int n0 = t8 * 8 + 2 * q4;
      float2* p0 = reinterpret_cast<float2*>(&h1b[(mbase + g4) * H1S + n0]);
      float2* p1 = reinterpret_cast<float2*>(&h1b[(mbase + g4 + 8) * H1S + n0]);
      float2 f0 = *p0, f1 = *p1;
      f0.x += fmaxf(acc[t8][0], 0.0f);
      f0.y += fmaxf(acc[t8][1], 0.0f);
      f1.x += fmaxf(acc[t8][2], 0.0f);
      f1.y += fmaxf(acc[t8][3], 0.0f);
      *p0 = f0; *p1 = f1;
    }
  }
  __syncwarp();                      // phase1->2: own-warp rows only

  // ---- Phase 2: h2 GEMM via tf32 MMA (3-pass hi/lo) -----------------------
  {
    float acc[8][4];
    #pragma unroll
    for (int t8 = 0; t8 < 8; ++t8)
      #pragma unroll
      for (int j = 0; j < 4; ++j) acc[t8][j] = 0.0f;

    const float* h1b = &s.h1[pt][0];
    #pragma unroll
    for (int ks = 0; ks < 8; ++ks) {
      const int r0 = (mbase + g4) * H1S + ks * 8 + q4;
      const int r1 = r0 + 8 * H1S;
      const float a0 = h1b[r0],      a1v = h1b[r1];
      const float a2f = h1b[r0 + 4], a3v = h1b[r1 + 4];
      uint32 ah0, al0, ah1, al1, ah2, al2, ah3, al3;
      split_tf32(a0,  ah0, al0);
      split_tf32(a1v, ah1, al1);
      split_tf32(a2f, ah2, al2);
      split_tf32(a3v, ah3, al3);
      #pragma unroll
      for (int t8 = 0; t8 < 8; ++t8) {
        const float b0 = s.w.Wg2[ks * 8 + q4][t8 * 8 + g4];
        const float b1 = s.w.Wg2[ks * 8 + q4 + 4][t8 * 8 + g4];
        uint32 bh0, bl0, bh1, bl1;
        split_tf32(b0, bh0, bl0);
        split_tf32(b1, bh1, bl1);
        mma_tf32(acc[t8], ah0, ah1, ah2, ah3, bh0, bh1);
        mma_tf32(acc[t8], ah0, ah1, ah2, ah3, bl0, bl1);
        mma_tf32(acc[t8], al0, al1, al2, al3, bh0, bh1);
      }
    }

    // Epilogue: bias + ReLU, write h2 back into h1 (own k-rows, A is dead)
    float* h1b2 = &s.h1[pt][0];
    #pragma unroll
    for (int t8 = 0; t8 < 8; ++t8) {
      const int n0 = t8 * 8 + 2 * q4;
      const float2 bb2 = *reinterpret_cast<const float2*>(&s.bias2[n0]);
      float2 v0, v1;
      v0.x = fmaxf(acc[t8][0] + bb2.x, 0.0f);
      v0.y = fmaxf(acc[t8][1] + bb2.y, 0.0f);
      v1.x = fmaxf(acc[t8][2] + bb2.x, 0.0f);
      v1.y = fmaxf(acc[t8][3] + bb2.y, 0.0f);
      *reinterpret_cast<float2*>(&h1b2[(mbase + g4) * H1S + n0]) = v0;
      *reinterpret_cast<float2*>(&h1b2[(mbase + g4 + 8) * H1S + n0]) = v1;
    }
  }
  __syncthreads();                   // sync3: h2 complete everywhere; Wg2 dead

  // ---- Phase 3a: woutP fill (into Wg2 space) ------------------------------
  const int o = tp;
  const float bo = b_out[o];                   // prefetch phase-4 params
  const float lg = ln_g[o];
  const float lb = ln_b[o];
  {
    float* wp = s.w.woutP_raw;                 // paired layout, conflict-free STS
    for (int i = tid; i < CCH * CCH; i += NTHREADS) {
      const int oo = i >> 6, c = i & 63;
      wp[(c >> 1) * WO2S + oo * 2 + (c & 1)] = W_out[i];
    }
  }

  // ---- Phase 3b: column reduction over k (thread = channel), softmax ------
  {
    const float f_res = features[base_pn * CCH + o];   // residual, coalesced
    float sv = 0.0f, mv = 0.0f;                // h2 >= 0
    const float* h2col = &s.h1[pt][o];
    #pragma unroll
    for (int k = 0; k < KNB; ++k) {
      const float h = h2col[k * H1S];          // bank (4k + o) % 32: conflict-free
      sv = fmaf(h, s.Watt[k], sv);
      mv = fmaxf(mv, h);
    }

    // online-softmax combine across the point's 2 warps (b_att invariant)
    float mxw = sv;
    #pragma unroll
    for (int m = 16; m >= 1; m >>= 1)
      mxw = fmaxf(mxw, __shfl_xor_sync(0xffffffffu, mxw, m));
    float sew = expf(sv - mxw);
    #pragma unroll
    for (int m = 16; m >= 1; m >>= 1)
      sew += __shfl_xor_sync(0xffffffffu, sew, m);
    if (lane == 0) s.redC[pt][wip] = make_float2(mxw, sew);
    bar_pt(1 + pt);
    const float2 r0 = s.redC[pt][0];
    const float2 r1 = s.redC[pt][1];
    const float mx = fmaxf(r0.x, r1.x);
    const float se = r0.y * expf(r0.x - mx) + r1.y * expf(r1.x - mx);
    const float score = expf(sv - mx) / se;
    s.resv[pt][o] = score * mv + f_res;
  }
  __syncthreads();                   // sync4: woutP + resv published

  // ---- Phase 4: out GEMM (f32x2, paired weights) + LayerNorm + ReLU -------
  {
    const float* wp = s.w.woutP_raw;
    ull e2 = 0ULL;
    #pragma unroll
    for (int c4 = 0; c4 < 16; ++c4) {
      const ull r01 = *reinterpret_cast<const ull*>(&s.resv[pt][c4 * 4]);     // bcast
      const ull r23 = *reinterpret_cast<const ull*>(&s.resv[pt][c4 * 4 + 2]);
      const ull w01 = *reinterpret_cast<const ull*>(&wp[(2 * c4) * WO2S + 2 * o]);
      const ull w23 = *reinterpret_cast<const ull*>(&wp[(2 * c4 + 1) * WO2S + 2 * o]);
      fma2(e2, r01, w01);
      fma2(e2, r23, w23);
    }
    float2 ee = unpack2(e2);
    float acc = ee.x + ee.y + bo;

    float sum = acc, sq = acc * acc;
    #pragma unroll
    for (int m = 16; m >= 1; m >>= 1) {
      sum += __shfl_xor_sync(0xffffffffu, sum, m);
      sq  += __shfl_xor_sync(0xffffffffu, sq, m);
    }
    if (lane == 0) s.redC[pt][wip] = make_float2(sum, sq);
    bar_pt(1 + pt);                  // point-local exchange
    const float2 e0 = s.redC[pt][0];
    const float2 e1 = s.redC[pt][1];
    sum = e0.x + e1.x;
    sq  = e0.y + e1.y;

    const float mu  = sum * (1.0f / 64.0f);
    const float var = sq * (1.0f / 64.0f) - mu * mu;
    const float r   = rsqrtf(var + EPSF);
    const float y   = lg * (acc - mu) * r + lb;
    out[base_pn * CCH + o] = fmaxf(y, 0.0f);
  }
}

extern "C" void kernel_launch(void* const* d_in, const int* in_sizes, int n_in,
                              void* d_out, int out_size) {
  const float* points   = (const float*)d_in[0];
  const float* features = (const float*)d_in[1];
  const int*   gidx     = (const int*)  d_in[2];
  const float* W_pos    = (const float*)d_in[3];
  const float* b_pos    = (const float*)d_in[4];
  const float* bn1_g    = (const float*)d_in[5];
  const float* bn1_b    = (const float*)d_in[6];
  const float* bn1_m    = (const float*)d_in[7];
  const float* bn1_v    = (const float*)d_in[8];
  const float* W_gcm    = (const float*)d_in[9];
  const float* b_gcm    = (const float*)d_in[10];
  const float* bn2_g    = (const float*)d_in[11];
  const float* bn2_b    = (const float*)d_in[12];
  const float* bn2_m    = (const float*)d_in[13];
  const float* bn2_v    = (const float*)d_in[14];
  const float* W_att    = (const float*)d_in[15];
  // d_in[16] = b_att (scalar): softmax-invariant, unused.
  const float* W_out    = (const float*)d_in[17];
  const float* b_out    = (const float*)d_in[18];
  const float* ln_g     = (const float*)d_in[19];
  const float* ln_b     = (const float*)d_in[20];
  float* out = (float*)d_out;

  const size_t smem = sizeof(Smem);
  cudaFuncSetAttribute((const void*)bridgenet_kernel,
                       cudaFuncAttributeMaxDynamicSharedMemorySize, (int)smem);

  const int total_pts = 2 * NPTS;             // 32768
  dim3 grid(total_pts / PPB);                 // 8192 blocks
  bridgenet_kernel<<<grid, NTHREADS, smem>>>(
      points, features, gidx, W_pos, b_pos,
      bn1_g, bn1_b, bn1_m, bn1_v,
      W_gcm, b_gcm, bn2_g, bn2_b, bn2_m, bn2_v,
      W_att, W_out, b_out, ln_g, ln_b, out);
}